// round 11
// baseline (speedup 1.0000x reference)
#include <cuda_runtime.h>
#include <math_constants.h>

#define NT 1024
#define NEDGE 2000
#define MMB 25            // helper blocks (4 nodes each)

__device__ __align__(16) float g_xwl[6400];
__device__ __align__(16) float g_xwr[6400];
__device__ __align__(16) float g_xw2l[2000];
__device__ __align__(16) float g_xw2r[2000];
__device__ int g_done1 = 0, g_done2 = 0;

// block-0 layout (dynamic smem)
struct __align__(16) SM {
    float  bigA[10000];   // cnt/segsum -> xw2l|xw2r|h2p|xw3|tmp
    float  bigB[8000];    // src|dst|ew|col -> Tx1|Lh2|ass
    float  bigC[3400];    // pooled(1000)|Hc(400)|s2(2000)
    float  h2[2000];
    float  csr_w[2000];
    int    csr_src[2000];
    int    csr_dst[2000];
    float2 pl[2000];
    float2 pr[2000];
    float2 pg[2000];
    float  wbuf[4160];    // tail 1600 used: WG1|WC0|WC1|WC2
    int    rowptr[104];
    int    scanbuf[128];
    float  dis_l[100], dis_r[100], dis_g[100], dis_c[100];
    float  score[100], tanhv[64], qv[100], qr[100];
    int    node_idx[100], perm[64], ks[64];
    int    flag64;
};

// helper layout (same dynamic smem, different view)
struct __align__(16) HSM {
    float  xs[400];
    float  sxwl[6400];
    float  sxwr[6400];
    float  sWL2[1280];
    float  sWR2[1280];
    float  h1s[256];
    int    hsrc[2000];
    int    hdst[2000];
    float  hew[2000];
    unsigned long long dull[200];   // fixed-point deg: dl[0..99], dr[100..199]
    float  hdl[100], hdr[100];      // rsqrt'd dis values
    float2 spl[512];                // per-node lists, 128 slots each
    float2 spr[512];
    int    hcnt[4];
    int    hflag;
};

__device__ __forceinline__ float lrelu(float v) { return v > 0.f ? v : 0.01f * v; }
__device__ __forceinline__ float4 lrelu4(float4 v) {
    return make_float4(lrelu(v.x), lrelu(v.y), lrelu(v.z), lrelu(v.w));
}

__global__ __launch_bounds__(NT, 1) void brain_kernel(
    const float* __restrict__ x,
    const float* __restrict__ Wl1, const float* __restrict__ Wr1,
    const int* __restrict__ ei32, const float* __restrict__ ea,
    const float* __restrict__ bl1, const float* __restrict__ br1,
    const float* __restrict__ Wl2, const float* __restrict__ bl2,
    const float* __restrict__ Wr2, const float* __restrict__ br2,
    const float* __restrict__ Wg1, const float* __restrict__ bg1,
    const float* __restrict__ Wrel, const float* __restrict__ brel,
    const float* __restrict__ Wroot,
    const float* __restrict__ Wc0, const float* __restrict__ Wc1,
    const float* __restrict__ Wc2, const float* __restrict__ bc,
    float* __restrict__ out)
{
    const int tid = threadIdx.x;
    extern __shared__ char raw[];

    // ================= helper blocks (self-sufficient) =================
    if (blockIdx.x > 0) {
        HSM* H = (HSM*)raw;
        const int b = blockIdx.x - 1;
        const int i0 = b * 4;

        if (tid < 400) H->xs[tid] = x[b * 400 + tid];
        if (tid == 512) H->hflag = 0;
        if (tid >= 544 && tid < 744) H->dull[tid - 544] = 0ull;
        __syncthreads();

        // mm1 (warps 0-7) in parallel with dtype probe (warps 8+)
        if (tid < 256) {
            const int j = tid & 63, r = tid >> 6;
            float al = 0.f, ar = 0.f;
            for (int k = 0; k < 100; k++) {
                float xv = H->xs[r * 100 + k];
                al += xv * __ldg(&Wl1[k * 64 + j]);
                ar += xv * __ldg(&Wr1[k * 64 + j]);
            }
            const int row = i0 + r;
            g_xwl[row * 64 + j] = al;
            g_xwr[row * 64 + j] = ar;
        } else if (tid < 356) {
            if (ei32[2 * (tid - 256) + 1] != 0) atomicOr(&H->hflag, 1);
        }
        __threadfence();
        __syncthreads();
        if (tid == 0) atomicAdd(&g_done1, 1);

        // ---- local edge data (overlaps the done1 wait of other blocks) ----
        if (tid < 500) ((float4*)H->hew)[tid] = __ldg((const float4*)ea + tid);
        if (H->hflag == 0) {
            const longlong2* ei2 = (const longlong2*)ei32;
            for (int q = tid; q < 1000; q += NT) {
                longlong2 a = __ldg(ei2 + q);
                H->hsrc[2 * q] = (int)a.x; H->hsrc[2 * q + 1] = (int)a.y;
                longlong2 b2 = __ldg(ei2 + 1000 + q);
                H->hdst[2 * q] = (int)b2.x; H->hdst[2 * q + 1] = (int)b2.y;
            }
        } else {
            const int4* ei4 = (const int4*)ei32;
            for (int q = tid; q < 500; q += NT) {
                ((int4*)H->hsrc)[q] = __ldg(ei4 + q);
                ((int4*)H->hdst)[q] = __ldg(ei4 + 500 + q);
            }
        }
        __syncthreads();

        // degrees via deterministic fixed-point atomics (integer adds commute)
        for (int e = tid; e < NEDGE; e += NT) {
            int s = H->hsrc[e], d = H->hdst[e];
            unsigned long long q = (unsigned long long)((double)H->hew[e] * 4294967296.0);
            if (d < 50 && s < 50)   atomicAdd(&H->dull[d], q);
            if (d >= 50 && s >= 50) atomicAdd(&H->dull[100 + d], q);
        }
        __syncthreads();
        if (tid < 100) {
            float dl = (float)((double)H->dull[tid]       * (1.0 / 4294967296.0));
            float dr = (float)((double)H->dull[100 + tid] * (1.0 / 4294967296.0));
            H->hdl[tid] = rsqrtf(dl + 1.f);
            H->hdr[tid] = rsqrtf(dr + 1.f);
        }
        __syncthreads();

        // gather our 4 nodes' edges (warp-ballot ordered compaction, ascending e)
        if (tid < 128) {
            const int wnode = tid >> 5, lane = tid & 31;
            const int node = i0 + wnode;
            int cnt = 0;
            for (int base = 0; base < NEDGE; base += 32) {
                int e = base + lane;
                bool m = (e < NEDGE) && (H->hdst[e] == node);
                unsigned bal = __ballot_sync(0xffffffffu, m);
                if (m) {
                    int pos = cnt + __popc(bal & ((1u << lane) - 1u));
                    int s = H->hsrc[e];
                    float w = H->hew[e];
                    float cl = (s < 50 && node < 50)   ? H->hdl[s] * w * H->hdl[node] : 0.f;
                    float cr = (s >= 50 && node >= 50) ? H->hdr[s] * w * H->hdr[node] : 0.f;
                    float fs = __int_as_float(s);
                    H->spl[wnode * 128 + pos] = make_float2(cl, fs);
                    H->spr[wnode * 128 + pos] = make_float2(cr, fs);
                }
                cnt += __popc(bal);
            }
            if (lane == 0) H->hcnt[wnode] = cnt;
        } else {
            for (int i = tid - 128; i < 1280; i += NT - 128) {
                H->sWL2[i] = __ldg(&Wl2[i]);
                H->sWR2[i] = __ldg(&Wr2[i]);
            }
        }
        __syncthreads();

        // wait for all mm1 results, stage xw1 into smem
        if (tid == 0) {
            while (atomicAdd(&g_done1, 0) < MMB) { __nanosleep(64); }
            __threadfence();
        }
        __syncthreads();
        {
            float4* dl = (float4*)H->sxwl;
            float4* dr = (float4*)H->sxwr;
            const float4* sl = (const float4*)g_xwl;
            const float4* sr = (const float4*)g_xwr;
            for (int i = tid; i < 1600; i += NT) {
                dl[i] = sl[i];
                dr[i] = sr[i];
            }
        }
        __syncthreads();

        // layer-1 aggregation for our 4 nodes
        if (tid < 256) {
            const int nl = tid >> 6, f = tid & 63;
            const int i = i0 + nl;
            const bool left = (i < 50);
            const float*  xw = left ? H->sxwl : H->sxwr;
            const float2* sl = (left ? H->spl : H->spr) + nl * 128;
            const float d = left ? H->hdl[i] : H->hdr[i];
            float acc = d * d * xw[i * 64 + f] + __ldg(left ? &bl1[f] : &br1[f]);
            const int cnt = H->hcnt[nl];
            #pragma unroll 4
            for (int q = 0; q < cnt; q++) {
                float2 cs = sl[q];
                acc += cs.x * xw[__float_as_int(cs.y) * 64 + f];
            }
            H->h1s[nl * 64 + f] = lrelu(acc);
        }
        __syncthreads();

        // layer-2 matmul for our 4 nodes (both mats)
        if (tid < 160) {
            const int nl = tid / 40, sub = tid % 40;
            const int f = sub % 20;
            const bool isr = (sub >= 20);
            const float* W = isr ? H->sWR2 : H->sWL2;
            float acc = 0.f;
            #pragma unroll 8
            for (int k = 0; k < 64; k++)
                acc += H->h1s[nl * 64 + k] * W[k * 20 + f];
            if (isr) g_xw2r[(i0 + nl) * 20 + f] = acc;
            else     g_xw2l[(i0 + nl) * 20 + f] = acc;
        }
        __threadfence();
        __syncthreads();
        if (tid == 0) atomicAdd(&g_done2, 1);
        return;
    }

    // ================= block 0: the pipeline =================
    SM* S = (SM*)raw;

    int*   srcA = (int*)S->bigB;
    int*   dstA = srcA + 2000;
    float* ewA  = S->bigB + 4000;
    int*   colA = srcA + 6000;
    float* WG1 = S->wbuf + 2560;
    float* WC0 = S->wbuf + 2960;
    float* WC1 = S->wbuf + 3360;
    float* WC2 = S->wbuf + 3760;

    // ---- P0: probe dtype, load edges/weights, zero cnt ----
    if (tid == 0) S->flag64 = 0;
    if (tid < 128) S->scanbuf[tid] = 0;
    __syncthreads();
    if (tid < 100 && ei32[2 * tid + 1] != 0) atomicOr(&S->flag64, 1);
    if (tid < 500) ((float4*)ewA)[tid] = __ldg((const float4*)ea + tid);
    if (tid < 100) {
        ((float4*)WG1)[tid] = __ldg((const float4*)Wg1 + tid);
        ((float4*)WC0)[tid] = __ldg((const float4*)Wc0 + tid);
        ((float4*)WC1)[tid] = __ldg((const float4*)Wc1 + tid);
        ((float4*)WC2)[tid] = __ldg((const float4*)Wc2 + tid);
    }
    {
        float4* z = (float4*)S->bigA;   // zero cnt area
        for (int i = tid; i < 1250; i += NT) z[i] = make_float4(0.f, 0.f, 0.f, 0.f);
    }
    __syncthreads();
    if (S->flag64 == 0) {
        const longlong2* ei2 = (const longlong2*)ei32;
        for (int q = tid; q < 1000; q += NT) {
            longlong2 a = __ldg(ei2 + q);
            srcA[2 * q] = (int)a.x; srcA[2 * q + 1] = (int)a.y;
            longlong2 b2 = __ldg(ei2 + 1000 + q);
            dstA[2 * q] = (int)b2.x; dstA[2 * q + 1] = (int)b2.y;
        }
    } else {
        const int4* ei4 = (const int4*)ei32;
        for (int q = tid; q < 500; q += NT) {
            ((int4*)srcA)[q] = __ldg(ei4 + q);
            ((int4*)dstA)[q] = __ldg(ei4 + 500 + q);
        }
    }
    __syncthreads();

    // ---- P1: stable CSR by dst (u16 counting sort; 2-level parallel scan) ----
    unsigned short* cnt = (unsigned short*)S->bigA;
    int* segsum = (int*)(S->bigA + 5000);
    if (tid < 100) {
        unsigned short* row = cnt + tid * 100;
        const int e0 = tid * 20;
        #pragma unroll
        for (int e = e0; e < e0 + 20; e++) row[dstA[e]]++;
    }
    __syncthreads();
    if (tid < 1000) {
        const int d = tid % 100, seg = tid / 100;
        int s = 0;
        #pragma unroll
        for (int t = seg * 10; t < seg * 10 + 10; t++) s += cnt[t * 100 + d];
        segsum[seg * 100 + d] = s;
    }
    __syncthreads();
    if (tid < 100) {
        int s = 0;
        #pragma unroll
        for (int seg = 0; seg < 10; seg++) {
            int v = segsum[seg * 100 + tid];
            segsum[seg * 100 + tid] = s;
            s += v;
        }
        S->scanbuf[tid] = s;
    }
    __syncthreads();
    if (tid < 1000) {
        const int d = tid % 100, seg = tid / 100;
        int run = segsum[seg * 100 + d];
        #pragma unroll
        for (int t = seg * 10; t < seg * 10 + 10; t++) {
            int v = cnt[t * 100 + d];
            cnt[t * 100 + d] = (unsigned short)run;
            run += v;
        }
    }
    if ((tid >> 5) == 31) {     // FULL warp 31 scans 128 totals
        const int lt = tid & 31;
        const int base = lt * 4;
        int a0 = S->scanbuf[base], a1 = S->scanbuf[base + 1];
        int a2 = S->scanbuf[base + 2], a3 = S->scanbuf[base + 3];
        a1 += a0; a2 += a1; a3 += a2;
        int s = a3;
        #pragma unroll
        for (int off = 1; off < 32; off <<= 1) {
            int n = __shfl_up_sync(0xffffffffu, s, off);
            if (lt >= off) s += n;
        }
        int bs = s - a3;
        S->scanbuf[base] = bs + a0; S->scanbuf[base + 1] = bs + a1;
        S->scanbuf[base + 2] = bs + a2; S->scanbuf[base + 3] = bs + a3;
    }
    __syncthreads();
    if (tid < 100) S->rowptr[tid + 1] = S->scanbuf[tid];
    if (tid == 0) S->rowptr[0] = 0;
    __syncthreads();
    if (tid < 100) {
        unsigned short* row = cnt + tid * 100;
        const int e0 = tid * 20;
        for (int e = e0; e < e0 + 20; e++) {
            int d = dstA[e];
            colA[S->rowptr[d] + row[d]] = e;
            row[d]++;
        }
    }
    __syncthreads();

    // ---- P1.5: gather to CSR order ----
    for (int p = tid; p < NEDGE; p += NT) {
        int e = colA[p];
        S->csr_src[p] = srcA[e];
        S->csr_dst[p] = dstA[e];
        S->csr_w[p]   = ewA[e];
    }
    __syncthreads();

    // ---- P2: degrees + packed coefficients (local only) ----
    if (tid < 100) {
        float dl = 0.f, dr = 0.f, dg = 0.f;
        const int d = tid;
        #pragma unroll 4
        for (int p = S->rowptr[d]; p < S->rowptr[d + 1]; p++) {
            int s = S->csr_src[p]; float w = S->csr_w[p];
            dg += w;
            if (d < 50 && s < 50)   dl += w;
            if (d >= 50 && s >= 50) dr += w;
        }
        S->dis_l[d] = rsqrtf(dl + 1.f);
        S->dis_r[d] = rsqrtf(dr + 1.f);
        S->dis_g[d] = rsqrtf(dg + 1.f);
    }
    __syncthreads();
    for (int p = tid; p < NEDGE; p += NT) {
        int s = S->csr_src[p], d = S->csr_dst[p]; float w = S->csr_w[p];
        float cl = (s < 50 && d < 50)   ? S->dis_l[s] * w * S->dis_l[d] : 0.f;
        float cr = (s >= 50 && d >= 50) ? S->dis_r[s] * w * S->dis_r[d] : 0.f;
        float cg = S->dis_g[s] * w * S->dis_g[d];
        float fs = __int_as_float(s);
        S->pl[p] = make_float2(cl, fs);
        S->pr[p] = make_float2(cr, fs);
        S->pg[p] = make_float2(cg, fs);
    }
    __syncthreads();

    // ---- wait for helpers to deliver xw2, stage into smem ----
    if (tid == 0) {
        while (atomicAdd(&g_done2, 0) < MMB) { __nanosleep(32); }
        __threadfence();
    }
    __syncthreads();

    float* xw2l = S->bigA;
    float* xw2r = S->bigA + 2000;
    float* h2p  = S->bigA + 4000;
    float* xw3  = S->bigA + 6000;
    float* tmp  = S->bigA + 8000;
    if (tid < 500) {
        ((float4*)xw2l)[tid] = ((const float4*)g_xw2l)[tid];
        ((float4*)xw2r)[tid] = ((const float4*)g_xw2r)[tid];
    }
    __syncthreads();

    // ---- P6: layer-2 GCN aggregate ----
    if (tid < 500) {
        const int i = tid / 5, f0 = (tid % 5) * 4;
        const float* xw; const float2* pp; float di; const float* bias;
        if (i < 50) { xw = xw2l; pp = S->pl; di = S->dis_l[i]; bias = bl2; }
        else        { xw = xw2r; pp = S->pr; di = S->dis_r[i]; bias = br2; }
        float4 sv = *(const float4*)&xw[i * 20 + f0];
        float4 b4 = __ldg((const float4*)(bias + f0));
        float dd = di * di;
        float4 acc = make_float4(dd * sv.x + b4.x, dd * sv.y + b4.y,
                                 dd * sv.z + b4.z, dd * sv.w + b4.w);
        #pragma unroll 4
        for (int p = S->rowptr[i]; p < S->rowptr[i + 1]; p++) {
            float2 cs = pp[p];
            int s = __float_as_int(cs.y);
            float4 v = *(const float4*)&xw[s * 20 + f0];
            acc.x += cs.x * v.x; acc.y += cs.x * v.y;
            acc.z += cs.x * v.z; acc.w += cs.x * v.w;
        }
        *(float4*)&h2p[i * 20 + f0] = lrelu4(acc);
    }
    __syncthreads();

    // ---- P7: layer-3 dense matmul then global aggregate -> h2 ----
    if (tid < 500) {
        const int i = tid / 5, f0 = (tid % 5) * 4;
        float4 acc = make_float4(0.f, 0.f, 0.f, 0.f);
        for (int k = 0; k < 20; k++) {
            float hv = h2p[i * 20 + k];
            float4 w = *(const float4*)&WG1[k * 20 + f0];
            acc.x += hv * w.x; acc.y += hv * w.y; acc.z += hv * w.z; acc.w += hv * w.w;
        }
        *(float4*)&xw3[i * 20 + f0] = acc;
    }
    __syncthreads();
    if (tid < 500) {
        const int i = tid / 5, f0 = (tid % 5) * 4;
        float di = S->dis_g[i], dd = di * di;
        float4 sv = *(const float4*)&xw3[i * 20 + f0];
        float4 b4 = __ldg((const float4*)(bg1 + f0));
        float4 acc = make_float4(dd * sv.x + b4.x, dd * sv.y + b4.y,
                                 dd * sv.z + b4.z, dd * sv.w + b4.w);
        #pragma unroll 4
        for (int p = S->rowptr[i]; p < S->rowptr[i + 1]; p++) {
            float2 cs = S->pg[p];
            int s = __float_as_int(cs.y);
            float4 v = *(const float4*)&xw3[s * 20 + f0];
            acc.x += cs.x * v.x; acc.y += cs.x * v.y;
            acc.z += cs.x * v.z; acc.w += cs.x * v.w;
        }
        *(float4*)&S->h2[i * 20 + f0] = lrelu4(acc);
    }
    __syncthreads();

    // ---- P8: SAGPool score ----
    if (tid < 100) {
        float q = 0.f, qq = 0.f;
        for (int f0 = 0; f0 < 20; f0 += 4) {
            float4 h = *(const float4*)&S->h2[tid * 20 + f0];
            float4 a = __ldg((const float4*)(Wrel + f0));
            float4 b = __ldg((const float4*)(Wroot + f0));
            q  += h.x * a.x + h.y * a.y + h.z * a.z + h.w * a.w;
            qq += h.x * b.x + h.y * b.y + h.z * b.z + h.w * b.w;
        }
        S->qv[tid] = q; S->qr[tid] = qq;
    }
    __syncthreads();
    if (tid < 100) {
        float s = __ldg(&brel[0]) + S->qr[tid];
        #pragma unroll 4
        for (int p = S->rowptr[tid]; p < S->rowptr[tid + 1]; p++)
            s += S->qv[S->csr_src[p]];
        S->score[tid] = s;
    }
    __syncthreads();

    // ---- P9: top-k(50) rank counting ----
    if (tid < 100) {
        float si = S->score[tid];
        int r = 0;
        for (int j = 0; j < 100; j++) {
            float sj = S->score[j];
            if (sj > si || (sj == si && j < tid)) r++;
        }
        S->node_idx[tid] = (r < 50) ? r : -1;
        if (r < 50) { S->perm[r] = tid; S->tanhv[r] = tanhf(si); }
    }
    __syncthreads();

    // ---- P10: ks, dis_c, pooled ----
    float* pooled = S->bigC;
    float* Hc     = S->bigC + 1000;
    float* s2     = S->bigC + 1400;
    if (tid < 100) {
        int r = S->node_idx[tid];
        if (r >= 0) {
            int pos = 0;
            for (int j = 0; j < tid; j++) if (S->node_idx[j] >= 0) pos++;
            S->ks[pos] = tid;
            float d = 0.f;
            for (int p = S->rowptr[tid]; p < S->rowptr[tid + 1]; p++)
                if (S->node_idx[S->csr_src[p]] >= 0) d += 1.f;
            S->dis_c[r] = (d > 0.f) ? rsqrtf(d) : 0.f;
        }
    } else if (tid >= 512 && tid < 762) {
        const int t = tid - 512;
        const int r = t / 5, f0 = (t % 5) * 4;
        float4 v = *(const float4*)&S->h2[S->perm[r] * 20 + f0];
        float tv = S->tanhv[r];
        *(float4*)&pooled[r * 20 + f0] =
            make_float4(v.x * tv, v.y * tv, v.z * tv, v.w * tv);
    }
    __syncthreads();

    // ---- P10.5: Cheb packed coeffs ----
    for (int p = tid; p < NEDGE; p += NT) {
        int rs = S->node_idx[S->csr_src[p]];
        int rd = S->node_idx[S->csr_dst[p]];
        float c = 0.f; int off = 0;
        if (rs >= 0 && rd >= 0) { c = -S->dis_c[rs] * S->dis_c[rd]; off = rs * 20; }
        S->pl[p] = make_float2(c, __int_as_float(off));
    }
    __syncthreads();

    // ---- P11: Tx1 = Lhat(h2); Lh2 = Lhat(Tx1) ----
    float* Tx1 = S->bigB;
    float* Lh2 = S->bigB + 2000;
    float* ass = S->bigB + 4000;
    {
        float4 z4 = make_float4(0.f, 0.f, 0.f, 0.f);
        if (tid < 250) {
            const int rr = tid / 5, f0 = (tid % 5) * 4;
            const int i = S->perm[rr];
            float4 acc = z4;
            #pragma unroll 4
            for (int p = S->rowptr[i]; p < S->rowptr[i + 1]; p++) {
                float2 cs = S->pl[p];
                int off = __float_as_int(cs.y);
                float4 v = *(const float4*)&S->h2[off + f0];
                acc.x += cs.x * v.x; acc.y += cs.x * v.y;
                acc.z += cs.x * v.z; acc.w += cs.x * v.w;
            }
            *(float4*)&Tx1[rr * 20 + f0] = acc;
        } else if (tid < 500) {
            ((float4*)Tx1)[tid] = z4;
        } else if (tid < 750) {
            ((float4*)Lh2)[tid - 250] = z4;
        }
    }
    __syncthreads();
    if (tid < 250) {
        const int rr = tid / 5, f0 = (tid % 5) * 4;
        const int i = S->perm[rr];
        float4 acc = make_float4(0.f, 0.f, 0.f, 0.f);
        #pragma unroll 4
        for (int p = S->rowptr[i]; p < S->rowptr[i + 1]; p++) {
            float2 cs = S->pl[p];
            int off = __float_as_int(cs.y);
            float4 v = *(const float4*)&Tx1[off + f0];
            acc.x += cs.x * v.x; acc.y += cs.x * v.y;
            acc.z += cs.x * v.z; acc.w += cs.x * v.w;
        }
        *(float4*)&Lh2[rr * 20 + f0] = acc;
    }
    __syncthreads();

    // ---- P12: s_raw ----
    if (tid < 500) {
        const int i = tid / 5, f0 = (tid % 5) * 4;
        float4 acc = __ldg((const float4*)(bc + f0));
        for (int k = 0; k < 20; k++) {
            float t0 = S->h2[i * 20 + k];
            float t1 = Tx1[i * 20 + k];
            float t2 = 2.f * Lh2[i * 20 + k] - t0;
            float4 w0 = *(const float4*)&WC0[k * 20 + f0];
            float4 w1 = *(const float4*)&WC1[k * 20 + f0];
            float4 w2 = *(const float4*)&WC2[k * 20 + f0];
            acc.x += t0 * w0.x + t1 * w1.x + t2 * w2.x;
            acc.y += t0 * w0.y + t1 * w1.y + t2 * w2.y;
            acc.z += t0 * w0.z + t1 * w1.z + t2 * w2.z;
            acc.w += t0 * w0.w + t1 * w1.w + t2 * w2.w;
        }
        *(float4*)&ass[i * 20 + f0] = acc;
    }
    __syncthreads();

    // ---- P13: double softmax, warp-per-row ----
    {
        const int wid = tid >> 5, lane = tid & 31;
        const unsigned FULL = 0xffffffffu;
        for (int i = wid; i < 100; i += 32) {
            float v = (lane < 20) ? ass[i * 20 + lane] : -CUDART_INF_F;
            float m = v;
            #pragma unroll
            for (int off = 16; off; off >>= 1) m = fmaxf(m, __shfl_xor_sync(FULL, m, off));
            float e = (lane < 20) ? expf(v - m) : 0.f;
            float s = e;
            #pragma unroll
            for (int off = 16; off; off >>= 1) s += __shfl_xor_sync(FULL, s, off);
            float a1 = e / s;
            float a1m = (lane < 20) ? a1 : -CUDART_INF_F;
            float m2 = a1m;
            #pragma unroll
            for (int off = 16; off; off >>= 1) m2 = fmaxf(m2, __shfl_xor_sync(FULL, m2, off));
            float e2 = (lane < 20) ? expf(a1 - m2) : 0.f;
            float s2s = e2;
            #pragma unroll
            for (int off = 16; off; off >>= 1) s2s += __shfl_xor_sync(FULL, s2s, off);
            if (lane < 20) {
                ass[i * 20 + lane] = a1;
                s2[i * 20 + lane] = e2 / s2s;
            }
        }
    }
    __syncthreads();

    // ---- P14: H_coarse = s2^T @ h2 (split-i partials) ----
    if (tid < 200) {
        const int c = tid / 10, rem = tid % 10;
        const int f0 = (rem % 5) * 4, half = rem / 5;
        float4 acc = make_float4(0.f, 0.f, 0.f, 0.f);
        for (int i = half * 50; i < half * 50 + 50; i++) {
            float sv = s2[i * 20 + c];
            float4 h = *(const float4*)&S->h2[i * 20 + f0];
            acc.x += sv * h.x; acc.y += sv * h.y; acc.z += sv * h.z; acc.w += sv * h.w;
        }
        ((float4*)tmp)[tid] = acc;
    }
    __syncthreads();
    if (tid < 100) {
        const int c = tid / 5, fp = tid % 5;
        float4 a = ((float4*)tmp)[c * 10 + fp];
        float4 b = ((float4*)tmp)[c * 10 + 5 + fp];
        *(float4*)&Hc[c * 20 + fp * 4] =
            make_float4(a.x + b.x, a.y + b.y, a.z + b.z, a.w + b.w);
    }
    __syncthreads();

    // ---- P15: out = pooled + ass[ks] @ H_coarse ----
    if (tid < 250) {
        const int j = tid / 5, f0 = (tid % 5) * 4;
        float4 acc = *(const float4*)&pooled[j * 20 + f0];
        const int row = S->ks[j];
        for (int k = 0; k < 20; k++) {
            float a = ass[row * 20 + k];
            float4 h = *(const float4*)&Hc[k * 20 + f0];
            acc.x += a * h.x; acc.y += a * h.y; acc.z += a * h.z; acc.w += a * h.w;
        }
        *(float4*)&out[j * 20 + f0] = acc;
    }
    __syncthreads();
    // reset sync vars for next graph replay
    if (tid == 0) {
        atomicExch(&g_done1, 0);
        atomicExch(&g_done2, 0);
    }
}

extern "C" void kernel_launch(void* const* d_in, const int* in_sizes, int n_in,
                              void* d_out, int out_size)
{
    (void)in_sizes; (void)n_in; (void)out_size;
    const float* x    = (const float*)d_in[0];
    const int*   ei   = (const int*)d_in[1];
    const float* ea   = (const float*)d_in[2];
    const float* Wl1  = (const float*)d_in[4];
    const float* bl1  = (const float*)d_in[5];
    const float* Wr1  = (const float*)d_in[6];
    const float* br1  = (const float*)d_in[7];
    const float* Wl2  = (const float*)d_in[8];
    const float* bl2  = (const float*)d_in[9];
    const float* Wr2  = (const float*)d_in[10];
    const float* br2  = (const float*)d_in[11];
    const float* Wg1  = (const float*)d_in[12];
    const float* bg1  = (const float*)d_in[13];
    const float* Wrel = (const float*)d_in[14];
    const float* brel = (const float*)d_in[15];
    const float* Wroot= (const float*)d_in[16];
    const float* Wc0  = (const float*)d_in[17];
    const float* Wc1  = (const float*)d_in[18];
    const float* Wc2  = (const float*)d_in[19];
    const float* bc   = (const float*)d_in[20];

    size_t smem = sizeof(SM) > sizeof(HSM) ? sizeof(SM) : sizeof(HSM);
    cudaFuncSetAttribute(brain_kernel, cudaFuncAttributeMaxDynamicSharedMemorySize, (int)smem);
    brain_kernel<<<1 + MMB, NT, smem>>>(x, Wl1, Wr1, ei, ea, bl1, br1, Wl2, bl2,
                                        Wr2, br2, Wg1, bg1, Wrel, brel, Wroot,
                                        Wc0, Wc1, Wc2, bc, (float*)d_out);
}

// round 12
// speedup vs baseline: 1.0615x; 1.0615x over previous
#include <cuda_runtime.h>
#include <math_constants.h>

#define NT 1024
#define NEDGE 2000
#define MMB 25            // helper blocks (4 nodes each)
#define SLOTS 64          // fixed per-dst edge slots

__device__ __align__(16) float g_xwl[6400];
__device__ __align__(16) float g_xwr[6400];
__device__ __align__(16) float g_xw2l[2000];
__device__ __align__(16) float g_xw2r[2000];
__device__ __align__(16) float2 g_pl[100 * SLOTS];
__device__ __align__(16) float2 g_pr[100 * SLOTS];
__device__ int   g_deg[100];
__device__ float g_disl[100], g_disr[100];
__device__ int   g_done1 = 0, g_edge_flag = 0, g_done2 = 0;

// block-0 layout (dynamic smem)
struct __align__(16) SM {
    float  bigA[10000];   // cnt/segsum -> xw2l|xw2r|h2p|xw3|tmp
    float  bigB[8000];    // src|dst|ew|col -> Tx1|Lh2|ass
    float  bigC[3400];    // pooled(1000)|Hc(400)|s2(2000)
    float  h2[2000];
    float  csr_w[2000];
    int    csr_src[2000];
    int    csr_dst[2000];
    float2 pl[2000];
    float2 pr[2000];
    float2 pg[2000];
    float  wbuf[4160];    // tail 1600 used: WG1|WC0|WC1|WC2
    int    rowptr[104];
    int    scanbuf[128];
    float  dis_l[100], dis_r[100], dis_g[100], dis_c[100];
    float  score[100], tanhv[64], qv[100], qr[100];
    int    node_idx[100], perm[64], ks[64];
    int    flag64;
};

// helper layout (same dynamic smem, different view)
struct __align__(16) HSM {
    float  xs[400];
    float  sxwl[6400];
    float  sxwr[6400];
    float  sWL2[1280];
    float  sWR2[1280];
    float  h1s[256];
    float  sdis[4];
    float2 spl[4 * SLOTS];
    float2 spr[4 * SLOTS];
    int    scnt[4];
};

__device__ __forceinline__ float lrelu(float v) { return v > 0.f ? v : 0.01f * v; }
__device__ __forceinline__ float4 lrelu4(float4 v) {
    return make_float4(lrelu(v.x), lrelu(v.y), lrelu(v.z), lrelu(v.w));
}

__global__ __launch_bounds__(NT, 1) void brain_kernel(
    const float* __restrict__ x,
    const float* __restrict__ Wl1, const float* __restrict__ Wr1,
    const int* __restrict__ ei32, const float* __restrict__ ea,
    const float* __restrict__ bl1, const float* __restrict__ br1,
    const float* __restrict__ Wl2, const float* __restrict__ bl2,
    const float* __restrict__ Wr2, const float* __restrict__ br2,
    const float* __restrict__ Wg1, const float* __restrict__ bg1,
    const float* __restrict__ Wrel, const float* __restrict__ brel,
    const float* __restrict__ Wroot,
    const float* __restrict__ Wc0, const float* __restrict__ Wc1,
    const float* __restrict__ Wc2, const float* __restrict__ bc,
    float* __restrict__ out)
{
    const int tid = threadIdx.x;
    extern __shared__ char raw[];

    // ================= helper blocks =================
    if (blockIdx.x > 0) {
        HSM* H = (HSM*)raw;
        const int b = blockIdx.x - 1;
        const int i0 = b * 4;

        // stage 1: layer-1 matmul of 4 rows
        if (tid < 400) H->xs[tid] = x[b * 400 + tid];
        __syncthreads();
        if (tid < 256) {
            const int j = tid & 63, r = tid >> 6;
            float al = 0.f, ar = 0.f;
            for (int k = 0; k < 100; k++) {
                float xv = H->xs[r * 100 + k];
                al += xv * __ldg(&Wl1[k * 64 + j]);
                ar += xv * __ldg(&Wr1[k * 64 + j]);
            }
            const int row = i0 + r;
            g_xwl[row * 64 + j] = al;
            g_xwr[row * 64 + j] = ar;
        }
        __threadfence();
        __syncthreads();
        if (tid == 0) atomicAdd(&g_done1, 1);

        // prefetch layer-2 weights while waiting
        for (int i = tid; i < 1280; i += NT) {
            H->sWL2[i] = __ldg(&Wl2[i]);
            H->sWR2[i] = __ldg(&Wr2[i]);
        }
        if (tid == 0) {
            while (atomicAdd(&g_done1, 0) < MMB) { __nanosleep(64); }
            __threadfence();
        }
        __syncthreads();

        // stage full xw1 into smem
        {
            float4* dl = (float4*)H->sxwl;
            float4* dr = (float4*)H->sxwr;
            const float4* sl = (const float4*)g_xwl;
            const float4* sr = (const float4*)g_xwr;
            for (int i = tid; i < 1600; i += NT) {
                dl[i] = sl[i];
                dr[i] = sr[i];
            }
        }
        // wait for edge data from block 0
        if (tid == 0) {
            while (atomicAdd(&g_edge_flag, 0) == 0) { __nanosleep(64); }
            __threadfence();
        }
        __syncthreads();
        // fixed-slot slice load: addresses known statically -> full MLP, no rowptr dep
        if (tid < 256) {
            const int nl = tid >> 6, q = tid & 63;
            H->spl[nl * SLOTS + q] = g_pl[(i0 + nl) * SLOTS + q];
            H->spr[nl * SLOTS + q] = g_pr[(i0 + nl) * SLOTS + q];
        } else if (tid >= 256 && tid < 260) {
            H->scnt[tid - 256] = g_deg[i0 + (tid - 256)];
        } else if (tid >= 288 && tid < 292) {
            int i = i0 + (tid - 288);
            H->sdis[tid - 288] = (i < 50) ? g_disl[i] : g_disr[i];
        }
        __syncthreads();

        // layer-1 aggregation for our 4 nodes
        if (tid < 256) {
            const int nl = tid >> 6, f = tid & 63;
            const int i = i0 + nl;
            const bool left = (i < 50);
            const float*  xw = left ? H->sxwl : H->sxwr;
            const float2* sl = (left ? H->spl : H->spr) + nl * SLOTS;
            const float d = H->sdis[nl];
            float acc = d * d * xw[i * 64 + f] + __ldg(left ? &bl1[f] : &br1[f]);
            const int cnt = H->scnt[nl];
            #pragma unroll 4
            for (int q = 0; q < cnt; q++) {
                float2 cs = sl[q];
                acc += cs.x * xw[__float_as_int(cs.y) * 64 + f];
            }
            H->h1s[nl * 64 + f] = lrelu(acc);
        }
        __syncthreads();

        // layer-2 matmul for our 4 nodes (both mats)
        if (tid < 160) {
            const int nl = tid / 40, sub = tid % 40;
            const int f = sub % 20;
            const bool isr = (sub >= 20);
            const float* W = isr ? H->sWR2 : H->sWL2;
            float acc = 0.f;
            #pragma unroll 8
            for (int k = 0; k < 64; k++)
                acc += H->h1s[nl * 64 + k] * W[k * 20 + f];
            if (isr) g_xw2r[(i0 + nl) * 20 + f] = acc;
            else     g_xw2l[(i0 + nl) * 20 + f] = acc;
        }
        __threadfence();
        __syncthreads();
        if (tid == 0) atomicAdd(&g_done2, 1);
        return;
    }

    // ================= block 0: the pipeline =================
    SM* S = (SM*)raw;

    int*   srcA = (int*)S->bigB;
    int*   dstA = srcA + 2000;
    float* ewA  = S->bigB + 4000;
    int*   colA = srcA + 6000;
    float* WG1 = S->wbuf + 2560;
    float* WC0 = S->wbuf + 2960;
    float* WC1 = S->wbuf + 3360;
    float* WC2 = S->wbuf + 3760;

    // ---- P0: probe dtype, load edges/weights, zero cnt ----
    if (tid == 0) S->flag64 = 0;
    if (tid < 128) S->scanbuf[tid] = 0;
    __syncthreads();
    if (tid < 100 && ei32[2 * tid + 1] != 0) atomicOr(&S->flag64, 1);
    if (tid < 500) ((float4*)ewA)[tid] = __ldg((const float4*)ea + tid);
    if (tid < 100) {
        ((float4*)WG1)[tid] = __ldg((const float4*)Wg1 + tid);
        ((float4*)WC0)[tid] = __ldg((const float4*)Wc0 + tid);
        ((float4*)WC1)[tid] = __ldg((const float4*)Wc1 + tid);
        ((float4*)WC2)[tid] = __ldg((const float4*)Wc2 + tid);
    }
    {
        float4* z = (float4*)S->bigA;   // zero cnt area
        for (int i = tid; i < 1250; i += NT) z[i] = make_float4(0.f, 0.f, 0.f, 0.f);
    }
    __syncthreads();
    if (S->flag64 == 0) {
        const longlong2* ei2 = (const longlong2*)ei32;
        for (int q = tid; q < 1000; q += NT) {
            longlong2 a = __ldg(ei2 + q);
            srcA[2 * q] = (int)a.x; srcA[2 * q + 1] = (int)a.y;
            longlong2 b2 = __ldg(ei2 + 1000 + q);
            dstA[2 * q] = (int)b2.x; dstA[2 * q + 1] = (int)b2.y;
        }
    } else {
        const int4* ei4 = (const int4*)ei32;
        for (int q = tid; q < 500; q += NT) {
            ((int4*)srcA)[q] = __ldg(ei4 + q);
            ((int4*)dstA)[q] = __ldg(ei4 + 500 + q);
        }
    }
    __syncthreads();

    // ---- P1: stable CSR by dst (u16 counting sort; 2-level parallel scan) ----
    unsigned short* cnt = (unsigned short*)S->bigA;
    int* segsum = (int*)(S->bigA + 5000);
    if (tid < 100) {
        unsigned short* row = cnt + tid * 100;
        const int e0 = tid * 20;
        #pragma unroll
        for (int e = e0; e < e0 + 20; e++) row[dstA[e]]++;
    }
    __syncthreads();
    if (tid < 1000) {
        const int d = tid % 100, seg = tid / 100;
        int s = 0;
        #pragma unroll
        for (int t = seg * 10; t < seg * 10 + 10; t++) s += cnt[t * 100 + d];
        segsum[seg * 100 + d] = s;
    }
    __syncthreads();
    if (tid < 100) {
        int s = 0;
        #pragma unroll
        for (int seg = 0; seg < 10; seg++) {
            int v = segsum[seg * 100 + tid];
            segsum[seg * 100 + tid] = s;
            s += v;
        }
        S->scanbuf[tid] = s;
        g_deg[tid] = s;   // publish per-dst edge counts early
    }
    __syncthreads();
    if (tid < 1000) {
        const int d = tid % 100, seg = tid / 100;
        int run = segsum[seg * 100 + d];
        #pragma unroll
        for (int t = seg * 10; t < seg * 10 + 10; t++) {
            int v = cnt[t * 100 + d];
            cnt[t * 100 + d] = (unsigned short)run;
            run += v;
        }
    }
    if ((tid >> 5) == 31) {     // FULL warp 31 scans 128 totals
        const int lt = tid & 31;
        const int base = lt * 4;
        int a0 = S->scanbuf[base], a1 = S->scanbuf[base + 1];
        int a2 = S->scanbuf[base + 2], a3 = S->scanbuf[base + 3];
        a1 += a0; a2 += a1; a3 += a2;
        int s = a3;
        #pragma unroll
        for (int off = 1; off < 32; off <<= 1) {
            int n = __shfl_up_sync(0xffffffffu, s, off);
            if (lt >= off) s += n;
        }
        int bs = s - a3;
        S->scanbuf[base] = bs + a0; S->scanbuf[base + 1] = bs + a1;
        S->scanbuf[base + 2] = bs + a2; S->scanbuf[base + 3] = bs + a3;
    }
    __syncthreads();
    if (tid < 100) S->rowptr[tid + 1] = S->scanbuf[tid];
    if (tid == 0) S->rowptr[0] = 0;
    __syncthreads();
    if (tid < 100) {
        unsigned short* row = cnt + tid * 100;
        const int e0 = tid * 20;
        for (int e = e0; e < e0 + 20; e++) {
            int d = dstA[e];
            colA[S->rowptr[d] + row[d]] = e;
            row[d]++;
        }
    }
    __syncthreads();

    // ---- P1.5: gather to CSR order ----
    for (int p = tid; p < NEDGE; p += NT) {
        int e = colA[p];
        S->csr_src[p] = srcA[e];
        S->csr_dst[p] = dstA[e];
        S->csr_w[p]   = ewA[e];
    }
    __syncthreads();

    // ---- P2: degrees ----
    if (tid < 100) {
        float dl = 0.f, dr = 0.f, dg = 0.f;
        const int d = tid;
        #pragma unroll 4
        for (int p = S->rowptr[d]; p < S->rowptr[d + 1]; p++) {
            int s = S->csr_src[p]; float w = S->csr_w[p];
            dg += w;
            if (d < 50 && s < 50)   dl += w;
            if (d >= 50 && s >= 50) dr += w;
        }
        S->dis_l[d] = rsqrtf(dl + 1.f);
        S->dis_r[d] = rsqrtf(dr + 1.f);
        S->dis_g[d] = rsqrtf(dg + 1.f);
    }
    __syncthreads();
    // packed coefficients + fixed-slot publish to helpers
    for (int p = tid; p < NEDGE; p += NT) {
        int s = S->csr_src[p], d = S->csr_dst[p]; float w = S->csr_w[p];
        float cl = (s < 50 && d < 50)   ? S->dis_l[s] * w * S->dis_l[d] : 0.f;
        float cr = (s >= 50 && d >= 50) ? S->dis_r[s] * w * S->dis_r[d] : 0.f;
        float cg = S->dis_g[s] * w * S->dis_g[d];
        float fs = __int_as_float(s);
        float2 vl = make_float2(cl, fs);
        float2 vr = make_float2(cr, fs);
        S->pl[p] = vl; S->pr[p] = vr;
        S->pg[p] = make_float2(cg, fs);
        int slot = d * SLOTS + (p - S->rowptr[d]);   // CSR order within dst
        g_pl[slot] = vl; g_pr[slot] = vr;
    }
    if (tid < 100) { g_disl[tid] = S->dis_l[tid]; g_disr[tid] = S->dis_r[tid]; }
    __threadfence();
    __syncthreads();
    if (tid == 0) atomicExch(&g_edge_flag, 1);

    // ---- wait for helpers to deliver xw2, stage into smem ----
    if (tid == 0) {
        while (atomicAdd(&g_done2, 0) < MMB) { __nanosleep(32); }
        __threadfence();
    }
    __syncthreads();

    float* xw2l = S->bigA;
    float* xw2r = S->bigA + 2000;
    float* h2p  = S->bigA + 4000;
    float* xw3  = S->bigA + 6000;
    float* tmp  = S->bigA + 8000;
    if (tid < 500) {
        ((float4*)xw2l)[tid] = ((const float4*)g_xw2l)[tid];
        ((float4*)xw2r)[tid] = ((const float4*)g_xw2r)[tid];
    }
    __syncthreads();

    // ---- P6: layer-2 GCN aggregate ----
    if (tid < 500) {
        const int i = tid / 5, f0 = (tid % 5) * 4;
        const float* xw; const float2* pp; float di; const float* bias;
        if (i < 50) { xw = xw2l; pp = S->pl; di = S->dis_l[i]; bias = bl2; }
        else        { xw = xw2r; pp = S->pr; di = S->dis_r[i]; bias = br2; }
        float4 sv = *(const float4*)&xw[i * 20 + f0];
        float4 b4 = __ldg((const float4*)(bias + f0));
        float dd = di * di;
        float4 acc = make_float4(dd * sv.x + b4.x, dd * sv.y + b4.y,
                                 dd * sv.z + b4.z, dd * sv.w + b4.w);
        #pragma unroll 4
        for (int p = S->rowptr[i]; p < S->rowptr[i + 1]; p++) {
            float2 cs = pp[p];
            int s = __float_as_int(cs.y);
            float4 v = *(const float4*)&xw[s * 20 + f0];
            acc.x += cs.x * v.x; acc.y += cs.x * v.y;
            acc.z += cs.x * v.z; acc.w += cs.x * v.w;
        }
        *(float4*)&h2p[i * 20 + f0] = lrelu4(acc);
    }
    __syncthreads();

    // ---- P7: layer-3 dense matmul then global aggregate -> h2 ----
    if (tid < 500) {
        const int i = tid / 5, f0 = (tid % 5) * 4;
        float4 acc = make_float4(0.f, 0.f, 0.f, 0.f);
        for (int k = 0; k < 20; k++) {
            float hv = h2p[i * 20 + k];
            float4 w = *(const float4*)&WG1[k * 20 + f0];
            acc.x += hv * w.x; acc.y += hv * w.y; acc.z += hv * w.z; acc.w += hv * w.w;
        }
        *(float4*)&xw3[i * 20 + f0] = acc;
    }
    __syncthreads();
    if (tid < 500) {
        const int i = tid / 5, f0 = (tid % 5) * 4;
        float di = S->dis_g[i], dd = di * di;
        float4 sv = *(const float4*)&xw3[i * 20 + f0];
        float4 b4 = __ldg((const float4*)(bg1 + f0));
        float4 acc = make_float4(dd * sv.x + b4.x, dd * sv.y + b4.y,
                                 dd * sv.z + b4.z, dd * sv.w + b4.w);
        #pragma unroll 4
        for (int p = S->rowptr[i]; p < S->rowptr[i + 1]; p++) {
            float2 cs = S->pg[p];
            int s = __float_as_int(cs.y);
            float4 v = *(const float4*)&xw3[s * 20 + f0];
            acc.x += cs.x * v.x; acc.y += cs.x * v.y;
            acc.z += cs.x * v.z; acc.w += cs.x * v.w;
        }
        *(float4*)&S->h2[i * 20 + f0] = lrelu4(acc);
    }
    __syncthreads();

    // ---- P8: SAGPool score ----
    if (tid < 100) {
        float q = 0.f, qq = 0.f;
        for (int f0 = 0; f0 < 20; f0 += 4) {
            float4 h = *(const float4*)&S->h2[tid * 20 + f0];
            float4 a = __ldg((const float4*)(Wrel + f0));
            float4 b = __ldg((const float4*)(Wroot + f0));
            q  += h.x * a.x + h.y * a.y + h.z * a.z + h.w * a.w;
            qq += h.x * b.x + h.y * b.y + h.z * b.z + h.w * b.w;
        }
        S->qv[tid] = q; S->qr[tid] = qq;
    }
    __syncthreads();
    if (tid < 100) {
        float s = __ldg(&brel[0]) + S->qr[tid];
        #pragma unroll 4
        for (int p = S->rowptr[tid]; p < S->rowptr[tid + 1]; p++)
            s += S->qv[S->csr_src[p]];
        S->score[tid] = s;
    }
    __syncthreads();

    // ---- P9: top-k(50) rank counting ----
    if (tid < 100) {
        float si = S->score[tid];
        int r = 0;
        for (int j = 0; j < 100; j++) {
            float sj = S->score[j];
            if (sj > si || (sj == si && j < tid)) r++;
        }
        S->node_idx[tid] = (r < 50) ? r : -1;
        if (r < 50) { S->perm[r] = tid; S->tanhv[r] = tanhf(si); }
    }
    __syncthreads();

    // ---- P10: ks, dis_c, pooled ----
    float* pooled = S->bigC;
    float* Hc     = S->bigC + 1000;
    float* s2     = S->bigC + 1400;
    if (tid < 100) {
        int r = S->node_idx[tid];
        if (r >= 0) {
            int pos = 0;
            for (int j = 0; j < tid; j++) if (S->node_idx[j] >= 0) pos++;
            S->ks[pos] = tid;
            float d = 0.f;
            for (int p = S->rowptr[tid]; p < S->rowptr[tid + 1]; p++)
                if (S->node_idx[S->csr_src[p]] >= 0) d += 1.f;
            S->dis_c[r] = (d > 0.f) ? rsqrtf(d) : 0.f;
        }
    } else if (tid >= 512 && tid < 762) {
        const int t = tid - 512;
        const int r = t / 5, f0 = (t % 5) * 4;
        float4 v = *(const float4*)&S->h2[S->perm[r] * 20 + f0];
        float tv = S->tanhv[r];
        *(float4*)&pooled[r * 20 + f0] =
            make_float4(v.x * tv, v.y * tv, v.z * tv, v.w * tv);
    }
    __syncthreads();

    // ---- P10.5: Cheb packed coeffs ----
    for (int p = tid; p < NEDGE; p += NT) {
        int rs = S->node_idx[S->csr_src[p]];
        int rd = S->node_idx[S->csr_dst[p]];
        float c = 0.f; int off = 0;
        if (rs >= 0 && rd >= 0) { c = -S->dis_c[rs] * S->dis_c[rd]; off = rs * 20; }
        S->pl[p] = make_float2(c, __int_as_float(off));
    }
    __syncthreads();

    // ---- P11: Tx1 = Lhat(h2) (rows<50) + zeros + s_raw rows>=50 on idle threads ----
    float* Tx1 = S->bigB;
    float* Lh2 = S->bigB + 2000;
    float* ass = S->bigB + 4000;
    {
        float4 z4 = make_float4(0.f, 0.f, 0.f, 0.f);
        if (tid < 250) {
            const int rr = tid / 5, f0 = (tid % 5) * 4;
            const int i = S->perm[rr];
            float4 acc = z4;
            #pragma unroll 4
            for (int p = S->rowptr[i]; p < S->rowptr[i + 1]; p++) {
                float2 cs = S->pl[p];
                int off = __float_as_int(cs.y);
                float4 v = *(const float4*)&S->h2[off + f0];
                acc.x += cs.x * v.x; acc.y += cs.x * v.y;
                acc.z += cs.x * v.z; acc.w += cs.x * v.w;
            }
            *(float4*)&Tx1[rr * 20 + f0] = acc;
        } else if (tid < 500) {
            ((float4*)Tx1)[tid] = z4;          // Tx1 rows 50..99 = 0
        } else if (tid < 750) {
            ((float4*)Lh2)[tid - 250] = z4;    // Lh2 rows 50..99 = 0
        } else if (tid < 1000) {
            // s_raw rows 50..99: Tx1=Lh2=0 => t1=0, t2=-t0
            const int t = tid - 750;
            const int i = 50 + t / 5, f0 = (t % 5) * 4;
            float4 acc = __ldg((const float4*)(bc + f0));
            for (int k = 0; k < 20; k++) {
                float t0 = S->h2[i * 20 + k];
                float4 w0 = *(const float4*)&WC0[k * 20 + f0];
                float4 w2 = *(const float4*)&WC2[k * 20 + f0];
                acc.x += t0 * (w0.x - w2.x);
                acc.y += t0 * (w0.y - w2.y);
                acc.z += t0 * (w0.z - w2.z);
                acc.w += t0 * (w0.w - w2.w);
            }
            *(float4*)&ass[i * 20 + f0] = acc;
        }
    }
    __syncthreads();
    if (tid < 250) {
        const int rr = tid / 5, f0 = (tid % 5) * 4;
        const int i = S->perm[rr];
        float4 acc = make_float4(0.f, 0.f, 0.f, 0.f);
        #pragma unroll 4
        for (int p = S->rowptr[i]; p < S->rowptr[i + 1]; p++) {
            float2 cs = S->pl[p];
            int off = __float_as_int(cs.y);
            float4 v = *(const float4*)&Tx1[off + f0];
            acc.x += cs.x * v.x; acc.y += cs.x * v.y;
            acc.z += cs.x * v.z; acc.w += cs.x * v.w;
        }
        *(float4*)&Lh2[rr * 20 + f0] = acc;
    }
    __syncthreads();

    // ---- P12: s_raw rows < 50 only ----
    if (tid < 250) {
        const int i = tid / 5, f0 = (tid % 5) * 4;
        float4 acc = __ldg((const float4*)(bc + f0));
        for (int k = 0; k < 20; k++) {
            float t0 = S->h2[i * 20 + k];
            float t1 = Tx1[i * 20 + k];
            float t2 = 2.f * Lh2[i * 20 + k] - t0;
            float4 w0 = *(const float4*)&WC0[k * 20 + f0];
            float4 w1 = *(const float4*)&WC1[k * 20 + f0];
            float4 w2 = *(const float4*)&WC2[k * 20 + f0];
            acc.x += t0 * w0.x + t1 * w1.x + t2 * w2.x;
            acc.y += t0 * w0.y + t1 * w1.y + t2 * w2.y;
            acc.z += t0 * w0.z + t1 * w1.z + t2 * w2.z;
            acc.w += t0 * w0.w + t1 * w1.w + t2 * w2.w;
        }
        *(float4*)&ass[i * 20 + f0] = acc;
    }
    __syncthreads();

    // ---- P13: double softmax, warp-per-row ----
    {
        const int wid = tid >> 5, lane = tid & 31;
        const unsigned FULL = 0xffffffffu;
        for (int i = wid; i < 100; i += 32) {
            float v = (lane < 20) ? ass[i * 20 + lane] : -CUDART_INF_F;
            float m = v;
            #pragma unroll
            for (int off = 16; off; off >>= 1) m = fmaxf(m, __shfl_xor_sync(FULL, m, off));
            float e = (lane < 20) ? expf(v - m) : 0.f;
            float s = e;
            #pragma unroll
            for (int off = 16; off; off >>= 1) s += __shfl_xor_sync(FULL, s, off);
            float a1 = e / s;
            float a1m = (lane < 20) ? a1 : -CUDART_INF_F;
            float m2 = a1m;
            #pragma unroll
            for (int off = 16; off; off >>= 1) m2 = fmaxf(m2, __shfl_xor_sync(FULL, m2, off));
            float e2 = (lane < 20) ? expf(a1 - m2) : 0.f;
            float s2s = e2;
            #pragma unroll
            for (int off = 16; off; off >>= 1) s2s += __shfl_xor_sync(FULL, s2s, off);
            if (lane < 20) {
                ass[i * 20 + lane] = a1;
                s2[i * 20 + lane] = e2 / s2s;
            }
        }
    }
    __syncthreads();

    // ---- P14: H_coarse = s2^T @ h2 (split-i partials) ----
    if (tid < 200) {
        const int c = tid / 10, rem = tid % 10;
        const int f0 = (rem % 5) * 4, half = rem / 5;
        float4 acc = make_float4(0.f, 0.f, 0.f, 0.f);
        for (int i = half * 50; i < half * 50 + 50; i++) {
            float sv = s2[i * 20 + c];
            float4 h = *(const float4*)&S->h2[i * 20 + f0];
            acc.x += sv * h.x; acc.y += sv * h.y; acc.z += sv * h.z; acc.w += sv * h.w;
        }
        ((float4*)tmp)[tid] = acc;
    }
    __syncthreads();
    if (tid < 100) {
        const int c = tid / 5, fp = tid % 5;
        float4 a = ((float4*)tmp)[c * 10 + fp];
        float4 b = ((float4*)tmp)[c * 10 + 5 + fp];
        *(float4*)&Hc[c * 20 + fp * 4] =
            make_float4(a.x + b.x, a.y + b.y, a.z + b.z, a.w + b.w);
    }
    __syncthreads();

    // ---- P15: out = pooled + ass[ks] @ H_coarse ----
    if (tid < 250) {
        const int j = tid / 5, f0 = (tid % 5) * 4;
        float4 acc = *(const float4*)&pooled[j * 20 + f0];
        const int row = S->ks[j];
        for (int k = 0; k < 20; k++) {
            float a = ass[row * 20 + k];
            float4 h = *(const float4*)&Hc[k * 20 + f0];
            acc.x += a * h.x; acc.y += a * h.y; acc.z += a * h.z; acc.w += a * h.w;
        }
        *(float4*)&out[j * 20 + f0] = acc;
    }
    __syncthreads();
    // reset sync vars for next graph replay
    if (tid == 0) {
        atomicExch(&g_done1, 0);
        atomicExch(&g_done2, 0);
        atomicExch(&g_edge_flag, 0);
    }
}

extern "C" void kernel_launch(void* const* d_in, const int* in_sizes, int n_in,
                              void* d_out, int out_size)
{
    (void)in_sizes; (void)n_in; (void)out_size;
    const float* x    = (const float*)d_in[0];
    const int*   ei   = (const int*)d_in[1];
    const float* ea   = (const float*)d_in[2];
    const float* Wl1  = (const float*)d_in[4];
    const float* bl1  = (const float*)d_in[5];
    const float* Wr1  = (const float*)d_in[6];
    const float* br1  = (const float*)d_in[7];
    const float* Wl2  = (const float*)d_in[8];
    const float* bl2  = (const float*)d_in[9];
    const float* Wr2  = (const float*)d_in[10];
    const float* br2  = (const float*)d_in[11];
    const float* Wg1  = (const float*)d_in[12];
    const float* bg1  = (const float*)d_in[13];
    const float* Wrel = (const float*)d_in[14];
    const float* brel = (const float*)d_in[15];
    const float* Wroot= (const float*)d_in[16];
    const float* Wc0  = (const float*)d_in[17];
    const float* Wc1  = (const float*)d_in[18];
    const float* Wc2  = (const float*)d_in[19];
    const float* bc   = (const float*)d_in[20];

    size_t smem = sizeof(SM) > sizeof(HSM) ? sizeof(SM) : sizeof(HSM);
    cudaFuncSetAttribute(brain_kernel, cudaFuncAttributeMaxDynamicSharedMemorySize, (int)smem);
    brain_kernel<<<1 + MMB, NT, smem>>>(x, Wl1, Wr1, ei, ea, bl1, br1, Wl2, bl2,
                                        Wr2, br2, Wg1, bg1, Wrel, brel, Wroot,
                                        Wc0, Wc1, Wc2, bc, (float*)d_out);
}

// round 13
// speedup vs baseline: 1.1076x; 1.0434x over previous
#include <cuda_runtime.h>
#include <math_constants.h>

#define NT 1024
#define NEDGE 2000
#define MMB 25            // helper blocks (4 nodes each)
#define SLOTS 64          // fixed per-dst edge slots

__device__ __align__(16) float g_xwl[6400];
__device__ __align__(16) float g_xwr[6400];
__device__ __align__(16) float g_xw2l[2000];
__device__ __align__(16) float g_xw2r[2000];
__device__ __align__(16) float2 g_pl[100 * SLOTS];
__device__ __align__(16) float2 g_pr[100 * SLOTS];
__device__ int   g_deg[100];
__device__ float g_disl[100], g_disr[100];
__device__ int   g_done1 = 0, g_edge_flag = 0, g_done2 = 0;

// block-0 layout (dynamic smem)
struct __align__(16) SM {
    float  bigA[10000];   // cnt/segsum -> xw2l|xw2r|h2p|xw3|tmp
    float  bigB[8000];    // src|dst|ew|col -> Tx1|Lh2|ass
    float  bigC[3400];    // pooled(1000)|Hc(400)|s2(2000)
    float  h2[2000];
    float  csr_w[2000];
    int    csr_src[2000];
    int    csr_dst[2000];
    float2 pl[2000];
    float2 pr[2000];
    float2 pg[2000];
    float  wbuf[4160];    // tail 1600 used: WG1|WC0|WC1|WC2
    int    rowptr[104];
    int    scanbuf[128];
    float  dis_l[100], dis_r[100], dis_g[100], dis_c[100];
    float  score[100], tanhv[64], qv[100], qr[100];
    int    node_idx[100], perm[64], ks[64];
    int    flag64;
};

// helper layout (same dynamic smem, different view)
struct __align__(16) HSM {
    float  xs[400];
    float  sxwl[6400];
    float  sxwr[6400];
    float  sWL2[1280];
    float  sWR2[1280];
    float  h1s[256];
    float  sdis[4];
    float2 spl[4 * SLOTS];
    float2 spr[4 * SLOTS];
    int    scnt[4];
};

__device__ __forceinline__ float lrelu(float v) { return v > 0.f ? v : 0.01f * v; }
__device__ __forceinline__ float4 lrelu4(float4 v) {
    return make_float4(lrelu(v.x), lrelu(v.y), lrelu(v.z), lrelu(v.w));
}

__global__ __launch_bounds__(NT, 1) void brain_kernel(
    const float* __restrict__ x,
    const float* __restrict__ Wl1, const float* __restrict__ Wr1,
    const int* __restrict__ ei32, const float* __restrict__ ea,
    const float* __restrict__ bl1, const float* __restrict__ br1,
    const float* __restrict__ Wl2, const float* __restrict__ bl2,
    const float* __restrict__ Wr2, const float* __restrict__ br2,
    const float* __restrict__ Wg1, const float* __restrict__ bg1,
    const float* __restrict__ Wrel, const float* __restrict__ brel,
    const float* __restrict__ Wroot,
    const float* __restrict__ Wc0, const float* __restrict__ Wc1,
    const float* __restrict__ Wc2, const float* __restrict__ bc,
    float* __restrict__ out)
{
    const int tid = threadIdx.x;
    extern __shared__ char raw[];

    // ================= helper blocks =================
    if (blockIdx.x > 0) {
        HSM* H = (HSM*)raw;
        const int b = blockIdx.x - 1;
        const int i0 = b * 4;

        // stage 1: layer-1 matmul of 4 rows
        if (tid < 400) H->xs[tid] = x[b * 400 + tid];
        __syncthreads();
        if (tid < 256) {
            const int j = tid & 63, r = tid >> 6;
            float al = 0.f, ar = 0.f;
            for (int k = 0; k < 100; k++) {
                float xv = H->xs[r * 100 + k];
                al += xv * __ldg(&Wl1[k * 64 + j]);
                ar += xv * __ldg(&Wr1[k * 64 + j]);
            }
            const int row = i0 + r;
            g_xwl[row * 64 + j] = al;
            g_xwr[row * 64 + j] = ar;
        }
        __threadfence();
        __syncthreads();
        if (tid == 0) atomicAdd(&g_done1, 1);

        // prefetch layer-2 weights while waiting
        for (int i = tid; i < 1280; i += NT) {
            H->sWL2[i] = __ldg(&Wl2[i]);
            H->sWR2[i] = __ldg(&Wr2[i]);
        }
        if (tid == 0) {
            while (atomicAdd(&g_done1, 0) < MMB) { __nanosleep(64); }
            __threadfence();
        }
        __syncthreads();

        // stage full xw1 into smem
        {
            float4* dl = (float4*)H->sxwl;
            float4* dr = (float4*)H->sxwr;
            const float4* sl = (const float4*)g_xwl;
            const float4* sr = (const float4*)g_xwr;
            for (int i = tid; i < 1600; i += NT) {
                dl[i] = sl[i];
                dr[i] = sr[i];
            }
        }
        // wait for edge data from block 0
        if (tid == 0) {
            while (atomicAdd(&g_edge_flag, 0) == 0) { __nanosleep(64); }
            __threadfence();
        }
        __syncthreads();
        // fixed-slot slice load: addresses known statically -> full MLP, no rowptr dep
        if (tid < 256) {
            const int nl = tid >> 6, q = tid & 63;
            H->spl[nl * SLOTS + q] = g_pl[(i0 + nl) * SLOTS + q];
            H->spr[nl * SLOTS + q] = g_pr[(i0 + nl) * SLOTS + q];
        } else if (tid >= 256 && tid < 260) {
            H->scnt[tid - 256] = g_deg[i0 + (tid - 256)];
        } else if (tid >= 288 && tid < 292) {
            int i = i0 + (tid - 288);
            H->sdis[tid - 288] = (i < 50) ? g_disl[i] : g_disr[i];
        }
        __syncthreads();

        // layer-1 aggregation for our 4 nodes
        if (tid < 256) {
            const int nl = tid >> 6, f = tid & 63;
            const int i = i0 + nl;
            const bool left = (i < 50);
            const float*  xw = left ? H->sxwl : H->sxwr;
            const float2* sl = (left ? H->spl : H->spr) + nl * SLOTS;
            const float d = H->sdis[nl];
            float acc = d * d * xw[i * 64 + f] + __ldg(left ? &bl1[f] : &br1[f]);
            const int cnt = H->scnt[nl];
            #pragma unroll 4
            for (int q = 0; q < cnt; q++) {
                float2 cs = sl[q];
                acc += cs.x * xw[__float_as_int(cs.y) * 64 + f];
            }
            H->h1s[nl * 64 + f] = lrelu(acc);
        }
        __syncthreads();

        // layer-2 matmul for our 4 nodes (both mats)
        if (tid < 160) {
            const int nl = tid / 40, sub = tid % 40;
            const int f = sub % 20;
            const bool isr = (sub >= 20);
            const float* W = isr ? H->sWR2 : H->sWL2;
            float acc = 0.f;
            #pragma unroll 8
            for (int k = 0; k < 64; k++)
                acc += H->h1s[nl * 64 + k] * W[k * 20 + f];
            if (isr) g_xw2r[(i0 + nl) * 20 + f] = acc;
            else     g_xw2l[(i0 + nl) * 20 + f] = acc;
        }
        __threadfence();
        __syncthreads();
        if (tid == 0) atomicAdd(&g_done2, 1);
        return;
    }

    // ================= block 0: the pipeline =================
    SM* S = (SM*)raw;

    int*   srcA = (int*)S->bigB;
    int*   dstA = srcA + 2000;
    float* ewA  = S->bigB + 4000;
    int*   colA = srcA + 6000;
    float* WG1 = S->wbuf + 2560;
    float* WC0 = S->wbuf + 2960;
    float* WC1 = S->wbuf + 3360;
    float* WC2 = S->wbuf + 3760;

    // ---- P0: probe dtype, load edges/weights, zero cnt ----
    if (tid == 0) S->flag64 = 0;
    if (tid < 128) S->scanbuf[tid] = 0;
    __syncthreads();
    if (tid < 100 && ei32[2 * tid + 1] != 0) atomicOr(&S->flag64, 1);
    if (tid < 500) ((float4*)ewA)[tid] = __ldg((const float4*)ea + tid);
    if (tid < 100) {
        ((float4*)WG1)[tid] = __ldg((const float4*)Wg1 + tid);
        ((float4*)WC0)[tid] = __ldg((const float4*)Wc0 + tid);
        ((float4*)WC1)[tid] = __ldg((const float4*)Wc1 + tid);
        ((float4*)WC2)[tid] = __ldg((const float4*)Wc2 + tid);
    }
    {
        float4* z = (float4*)S->bigA;   // zero cnt area
        for (int i = tid; i < 1250; i += NT) z[i] = make_float4(0.f, 0.f, 0.f, 0.f);
    }
    __syncthreads();
    if (S->flag64 == 0) {
        const longlong2* ei2 = (const longlong2*)ei32;
        for (int q = tid; q < 1000; q += NT) {
            longlong2 a = __ldg(ei2 + q);
            srcA[2 * q] = (int)a.x; srcA[2 * q + 1] = (int)a.y;
            longlong2 b2 = __ldg(ei2 + 1000 + q);
            dstA[2 * q] = (int)b2.x; dstA[2 * q + 1] = (int)b2.y;
        }
    } else {
        const int4* ei4 = (const int4*)ei32;
        for (int q = tid; q < 500; q += NT) {
            ((int4*)srcA)[q] = __ldg(ei4 + q);
            ((int4*)dstA)[q] = __ldg(ei4 + 500 + q);
        }
    }
    __syncthreads();

    // ---- P1: stable CSR by dst (u16 counting sort; 2-level parallel scan) ----
    unsigned short* cnt = (unsigned short*)S->bigA;
    int* segsum = (int*)(S->bigA + 5000);
    if (tid < 100) {
        unsigned short* row = cnt + tid * 100;
        const int e0 = tid * 20;
        #pragma unroll
        for (int e = e0; e < e0 + 20; e++) row[dstA[e]]++;
    }
    __syncthreads();
    if (tid < 1000) {
        const int d = tid % 100, seg = tid / 100;
        int s = 0;
        #pragma unroll
        for (int t = seg * 10; t < seg * 10 + 10; t++) s += cnt[t * 100 + d];
        segsum[seg * 100 + d] = s;
    }
    __syncthreads();
    if (tid < 100) {
        int s = 0;
        #pragma unroll
        for (int seg = 0; seg < 10; seg++) {
            int v = segsum[seg * 100 + tid];
            segsum[seg * 100 + tid] = s;
            s += v;
        }
        S->scanbuf[tid] = s;
        g_deg[tid] = s;   // publish per-dst edge counts early
    }
    __syncthreads();
    if (tid < 1000) {
        const int d = tid % 100, seg = tid / 100;
        int run = segsum[seg * 100 + d];
        #pragma unroll
        for (int t = seg * 10; t < seg * 10 + 10; t++) {
            int v = cnt[t * 100 + d];
            cnt[t * 100 + d] = (unsigned short)run;
            run += v;
        }
    }
    if ((tid >> 5) == 31) {     // FULL warp 31 scans 128 totals, writes rowptr direct
        const int lt = tid & 31;
        const int base = lt * 4;
        int a0 = S->scanbuf[base], a1 = S->scanbuf[base + 1];
        int a2 = S->scanbuf[base + 2], a3 = S->scanbuf[base + 3];
        a1 += a0; a2 += a1; a3 += a2;
        int s = a3;
        #pragma unroll
        for (int off = 1; off < 32; off <<= 1) {
            int n = __shfl_up_sync(0xffffffffu, s, off);
            if (lt >= off) s += n;
        }
        int bs = s - a3;
        if (base + 1 <= 100) S->rowptr[base + 1] = bs + a0;
        if (base + 2 <= 100) S->rowptr[base + 2] = bs + a1;
        if (base + 3 <= 100) S->rowptr[base + 3] = bs + a2;
        if (base + 4 <= 100) S->rowptr[base + 4] = bs + a3;
        if (lt == 0) S->rowptr[0] = 0;
    }
    __syncthreads();
    if (tid < 100) {
        unsigned short* row = cnt + tid * 100;
        const int e0 = tid * 20;
        for (int e = e0; e < e0 + 20; e++) {
            int d = dstA[e];
            colA[S->rowptr[d] + row[d]] = e;
            row[d]++;
        }
    }
    __syncthreads();

    // ---- P1.5+P2a: gather to CSR order (tid>=128) & degrees via colA (tid<100) ----
    if (tid >= 128) {
        for (int p = tid - 128; p < NEDGE; p += NT - 128) {
            int e = colA[p];
            S->csr_src[p] = srcA[e];
            S->csr_dst[p] = dstA[e];
            S->csr_w[p]   = ewA[e];
        }
    } else if (tid < 100) {
        float dl = 0.f, dr = 0.f, dg = 0.f;
        const int d = tid;
        #pragma unroll 4
        for (int p = S->rowptr[d]; p < S->rowptr[d + 1]; p++) {
            int e = colA[p];
            int s = srcA[e]; float w = ewA[e];
            dg += w;
            if (d < 50 && s < 50)   dl += w;
            if (d >= 50 && s >= 50) dr += w;
        }
        S->dis_l[d] = rsqrtf(dl + 1.f);
        S->dis_r[d] = rsqrtf(dr + 1.f);
        S->dis_g[d] = rsqrtf(dg + 1.f);
    }
    __syncthreads();

    // ---- P2b: packed coefficients + fixed-slot publish to helpers ----
    for (int p = tid; p < NEDGE; p += NT) {
        int s = S->csr_src[p], d = S->csr_dst[p]; float w = S->csr_w[p];
        float cl = (s < 50 && d < 50)   ? S->dis_l[s] * w * S->dis_l[d] : 0.f;
        float cr = (s >= 50 && d >= 50) ? S->dis_r[s] * w * S->dis_r[d] : 0.f;
        float cg = S->dis_g[s] * w * S->dis_g[d];
        float fs = __int_as_float(s);
        float2 vl = make_float2(cl, fs);
        float2 vr = make_float2(cr, fs);
        S->pl[p] = vl; S->pr[p] = vr;
        S->pg[p] = make_float2(cg, fs);
        int slot = d * SLOTS + (p - S->rowptr[d]);   // CSR order within dst
        g_pl[slot] = vl; g_pr[slot] = vr;
    }
    if (tid < 100) { g_disl[tid] = S->dis_l[tid]; g_disr[tid] = S->dis_r[tid]; }
    __threadfence();
    __syncthreads();
    if (tid == 0) atomicExch(&g_edge_flag, 1);

    // ---- wait for helpers to deliver xw2, stage into smem ----
    if (tid == 0) {
        while (atomicAdd(&g_done2, 0) < MMB) { __nanosleep(32); }
        __threadfence();
    }
    __syncthreads();

    float* xw2l = S->bigA;
    float* xw2r = S->bigA + 2000;
    float* h2p  = S->bigA + 4000;
    float* xw3  = S->bigA + 6000;
    float* tmp  = S->bigA + 8000;
    if (tid < 500) {
        ((float4*)xw2l)[tid] = ((const float4*)g_xw2l)[tid];
        ((float4*)xw2r)[tid] = ((const float4*)g_xw2r)[tid];
    }
    __syncthreads();

    // ---- P6: layer-2 GCN aggregate ----
    if (tid < 500) {
        const int i = tid / 5, f0 = (tid % 5) * 4;
        const float* xw; const float2* pp; float di; const float* bias;
        if (i < 50) { xw = xw2l; pp = S->pl; di = S->dis_l[i]; bias = bl2; }
        else        { xw = xw2r; pp = S->pr; di = S->dis_r[i]; bias = br2; }
        float4 sv = *(const float4*)&xw[i * 20 + f0];
        float4 b4 = __ldg((const float4*)(bias + f0));
        float dd = di * di;
        float4 acc = make_float4(dd * sv.x + b4.x, dd * sv.y + b4.y,
                                 dd * sv.z + b4.z, dd * sv.w + b4.w);
        #pragma unroll 4
        for (int p = S->rowptr[i]; p < S->rowptr[i + 1]; p++) {
            float2 cs = pp[p];
            int s = __float_as_int(cs.y);
            float4 v = *(const float4*)&xw[s * 20 + f0];
            acc.x += cs.x * v.x; acc.y += cs.x * v.y;
            acc.z += cs.x * v.z; acc.w += cs.x * v.w;
        }
        *(float4*)&h2p[i * 20 + f0] = lrelu4(acc);
    }
    __syncthreads();

    // ---- P7: layer-3 dense matmul then global aggregate -> h2 ----
    if (tid < 500) {
        const int i = tid / 5, f0 = (tid % 5) * 4;
        float4 acc = make_float4(0.f, 0.f, 0.f, 0.f);
        for (int k = 0; k < 20; k++) {
            float hv = h2p[i * 20 + k];
            float4 w = *(const float4*)&WG1[k * 20 + f0];
            acc.x += hv * w.x; acc.y += hv * w.y; acc.z += hv * w.z; acc.w += hv * w.w;
        }
        *(float4*)&xw3[i * 20 + f0] = acc;
    }
    __syncthreads();
    if (tid < 500) {
        const int i = tid / 5, f0 = (tid % 5) * 4;
        float di = S->dis_g[i], dd = di * di;
        float4 sv = *(const float4*)&xw3[i * 20 + f0];
        float4 b4 = __ldg((const float4*)(bg1 + f0));
        float4 acc = make_float4(dd * sv.x + b4.x, dd * sv.y + b4.y,
                                 dd * sv.z + b4.z, dd * sv.w + b4.w);
        #pragma unroll 4
        for (int p = S->rowptr[i]; p < S->rowptr[i + 1]; p++) {
            float2 cs = S->pg[p];
            int s = __float_as_int(cs.y);
            float4 v = *(const float4*)&xw3[s * 20 + f0];
            acc.x += cs.x * v.x; acc.y += cs.x * v.y;
            acc.z += cs.x * v.z; acc.w += cs.x * v.w;
        }
        *(float4*)&S->h2[i * 20 + f0] = lrelu4(acc);
    }
    __syncthreads();

    // ---- P8: SAGPool score ----
    if (tid < 100) {
        float q = 0.f, qq = 0.f;
        for (int f0 = 0; f0 < 20; f0 += 4) {
            float4 h = *(const float4*)&S->h2[tid * 20 + f0];
            float4 a = __ldg((const float4*)(Wrel + f0));
            float4 b = __ldg((const float4*)(Wroot + f0));
            q  += h.x * a.x + h.y * a.y + h.z * a.z + h.w * a.w;
            qq += h.x * b.x + h.y * b.y + h.z * b.z + h.w * b.w;
        }
        S->qv[tid] = q; S->qr[tid] = qq;
    }
    __syncthreads();
    if (tid < 100) {
        float s = __ldg(&brel[0]) + S->qr[tid];
        #pragma unroll 4
        for (int p = S->rowptr[tid]; p < S->rowptr[tid + 1]; p++)
            s += S->qv[S->csr_src[p]];
        S->score[tid] = s;
    }
    __syncthreads();

    // ---- P9: top-k(50) rank counting ----
    if (tid < 100) {
        float si = S->score[tid];
        int r = 0;
        for (int j = 0; j < 100; j++) {
            float sj = S->score[j];
            if (sj > si || (sj == si && j < tid)) r++;
        }
        S->node_idx[tid] = (r < 50) ? r : -1;
        if (r < 50) { S->perm[r] = tid; S->tanhv[r] = tanhf(si); }
    }
    __syncthreads();

    // ---- P10: ks, dis_c, pooled ----
    float* pooled = S->bigC;
    float* Hc     = S->bigC + 1000;
    float* s2     = S->bigC + 1400;
    if (tid < 100) {
        int r = S->node_idx[tid];
        if (r >= 0) {
            int pos = 0;
            for (int j = 0; j < tid; j++) if (S->node_idx[j] >= 0) pos++;
            S->ks[pos] = tid;
            float d = 0.f;
            for (int p = S->rowptr[tid]; p < S->rowptr[tid + 1]; p++)
                if (S->node_idx[S->csr_src[p]] >= 0) d += 1.f;
            S->dis_c[r] = (d > 0.f) ? rsqrtf(d) : 0.f;
        }
    } else if (tid >= 512 && tid < 762) {
        const int t = tid - 512;
        const int r = t / 5, f0 = (t % 5) * 4;
        float4 v = *(const float4*)&S->h2[S->perm[r] * 20 + f0];
        float tv = S->tanhv[r];
        *(float4*)&pooled[r * 20 + f0] =
            make_float4(v.x * tv, v.y * tv, v.z * tv, v.w * tv);
    }
    __syncthreads();

    // ---- P10.5: Cheb packed coeffs ----
    for (int p = tid; p < NEDGE; p += NT) {
        int rs = S->node_idx[S->csr_src[p]];
        int rd = S->node_idx[S->csr_dst[p]];
        float c = 0.f; int off = 0;
        if (rs >= 0 && rd >= 0) { c = -S->dis_c[rs] * S->dis_c[rd]; off = rs * 20; }
        S->pl[p] = make_float2(c, __int_as_float(off));
    }
    __syncthreads();

    // ---- P11: Tx1 = Lhat(h2) (rows<50) + zeros + s_raw rows>=50 on idle threads ----
    float* Tx1 = S->bigB;
    float* Lh2 = S->bigB + 2000;
    float* ass = S->bigB + 4000;
    {
        float4 z4 = make_float4(0.f, 0.f, 0.f, 0.f);
        if (tid < 250) {
            const int rr = tid / 5, f0 = (tid % 5) * 4;
            const int i = S->perm[rr];
            float4 acc = z4;
            #pragma unroll 4
            for (int p = S->rowptr[i]; p < S->rowptr[i + 1]; p++) {
                float2 cs = S->pl[p];
                int off = __float_as_int(cs.y);
                float4 v = *(const float4*)&S->h2[off + f0];
                acc.x += cs.x * v.x; acc.y += cs.x * v.y;
                acc.z += cs.x * v.z; acc.w += cs.x * v.w;
            }
            *(float4*)&Tx1[rr * 20 + f0] = acc;
        } else if (tid < 500) {
            ((float4*)Tx1)[tid] = z4;          // Tx1 rows 50..99 = 0
        } else if (tid < 750) {
            ((float4*)Lh2)[tid - 250] = z4;    // Lh2 rows 50..99 = 0
        } else if (tid < 1000) {
            // s_raw rows 50..99: Tx1=Lh2=0 => t1=0, t2=-t0
            const int t = tid - 750;
            const int i = 50 + t / 5, f0 = (t % 5) * 4;
            float4 acc = __ldg((const float4*)(bc + f0));
            for (int k = 0; k < 20; k++) {
                float t0 = S->h2[i * 20 + k];
                float4 w0 = *(const float4*)&WC0[k * 20 + f0];
                float4 w2 = *(const float4*)&WC2[k * 20 + f0];
                acc.x += t0 * (w0.x - w2.x);
                acc.y += t0 * (w0.y - w2.y);
                acc.z += t0 * (w0.z - w2.z);
                acc.w += t0 * (w0.w - w2.w);
            }
            *(float4*)&ass[i * 20 + f0] = acc;
        }
    }
    __syncthreads();
    if (tid < 250) {
        const int rr = tid / 5, f0 = (tid % 5) * 4;
        const int i = S->perm[rr];
        float4 acc = make_float4(0.f, 0.f, 0.f, 0.f);
        #pragma unroll 4
        for (int p = S->rowptr[i]; p < S->rowptr[i + 1]; p++) {
            float2 cs = S->pl[p];
            int off = __float_as_int(cs.y);
            float4 v = *(const float4*)&Tx1[off + f0];
            acc.x += cs.x * v.x; acc.y += cs.x * v.y;
            acc.z += cs.x * v.z; acc.w += cs.x * v.w;
        }
        *(float4*)&Lh2[rr * 20 + f0] = acc;
    }
    __syncthreads();

    // ---- P12: s_raw rows < 50 only ----
    if (tid < 250) {
        const int i = tid / 5, f0 = (tid % 5) * 4;
        float4 acc = __ldg((const float4*)(bc + f0));
        for (int k = 0; k < 20; k++) {
            float t0 = S->h2[i * 20 + k];
            float t1 = Tx1[i * 20 + k];
            float t2 = 2.f * Lh2[i * 20 + k] - t0;
            float4 w0 = *(const float4*)&WC0[k * 20 + f0];
            float4 w1 = *(const float4*)&WC1[k * 20 + f0];
            float4 w2 = *(const float4*)&WC2[k * 20 + f0];
            acc.x += t0 * w0.x + t1 * w1.x + t2 * w2.x;
            acc.y += t0 * w0.y + t1 * w1.y + t2 * w2.y;
            acc.z += t0 * w0.z + t1 * w1.z + t2 * w2.z;
            acc.w += t0 * w0.w + t1 * w1.w + t2 * w2.w;
        }
        *(float4*)&ass[i * 20 + f0] = acc;
    }
    __syncthreads();

    // ---- P13: double softmax, warp-per-row (no 2nd max: a1 in (0,1]) ----
    {
        const int wid = tid >> 5, lane = tid & 31;
        const unsigned FULL = 0xffffffffu;
        for (int i = wid; i < 100; i += 32) {
            float v = (lane < 20) ? ass[i * 20 + lane] : -CUDART_INF_F;
            float m = v;
            #pragma unroll
            for (int off = 16; off; off >>= 1) m = fmaxf(m, __shfl_xor_sync(FULL, m, off));
            float e = (lane < 20) ? expf(v - m) : 0.f;
            float s = e;
            #pragma unroll
            for (int off = 16; off; off >>= 1) s += __shfl_xor_sync(FULL, s, off);
            float a1 = e / s;
            float e2 = (lane < 20) ? expf(a1) : 0.f;   // a1<=1, overflow-safe
            float s2s = e2;
            #pragma unroll
            for (int off = 16; off; off >>= 1) s2s += __shfl_xor_sync(FULL, s2s, off);
            if (lane < 20) {
                ass[i * 20 + lane] = a1;
                s2[i * 20 + lane] = e2 / s2s;
            }
        }
    }
    __syncthreads();

    // ---- P14: H_coarse = s2^T @ h2 (split-i partials) ----
    if (tid < 200) {
        const int c = tid / 10, rem = tid % 10;
        const int f0 = (rem % 5) * 4, half = rem / 5;
        float4 acc = make_float4(0.f, 0.f, 0.f, 0.f);
        for (int i = half * 50; i < half * 50 + 50; i++) {
            float sv = s2[i * 20 + c];
            float4 h = *(const float4*)&S->h2[i * 20 + f0];
            acc.x += sv * h.x; acc.y += sv * h.y; acc.z += sv * h.z; acc.w += sv * h.w;
        }
        ((float4*)tmp)[tid] = acc;
    }
    __syncthreads();
    if (tid < 100) {
        const int c = tid / 5, fp = tid % 5;
        float4 a = ((float4*)tmp)[c * 10 + fp];
        float4 b = ((float4*)tmp)[c * 10 + 5 + fp];
        *(float4*)&Hc[c * 20 + fp * 4] =
            make_float4(a.x + b.x, a.y + b.y, a.z + b.z, a.w + b.w);
    }
    __syncthreads();

    // ---- P15: out = pooled + ass[ks] @ H_coarse ----
    if (tid < 250) {
        const int j = tid / 5, f0 = (tid % 5) * 4;
        float4 acc = *(const float4*)&pooled[j * 20 + f0];
        const int row = S->ks[j];
        for (int k = 0; k < 20; k++) {
            float a = ass[row * 20 + k];
            float4 h = *(const float4*)&Hc[k * 20 + f0];
            acc.x += a * h.x; acc.y += a * h.y; acc.z += a * h.z; acc.w += a * h.w;
        }
        *(float4*)&out[j * 20 + f0] = acc;
    }
    __syncthreads();
    // reset sync vars for next graph replay
    if (tid == 0) {
        atomicExch(&g_done1, 0);
        atomicExch(&g_done2, 0);
        atomicExch(&g_edge_flag, 0);
    }
}

extern "C" void kernel_launch(void* const* d_in, const int* in_sizes, int n_in,
                              void* d_out, int out_size)
{
    (void)in_sizes; (void)n_in; (void)out_size;
    const float* x    = (const float*)d_in[0];
    const int*   ei   = (const int*)d_in[1];
    const float* ea   = (const float*)d_in[2];
    const float* Wl1  = (const float*)d_in[4];
    const float* bl1  = (const float*)d_in[5];
    const float* Wr1  = (const float*)d_in[6];
    const float* br1  = (const float*)d_in[7];
    const float* Wl2  = (const float*)d_in[8];
    const float* bl2  = (const float*)d_in[9];
    const float* Wr2  = (const float*)d_in[10];
    const float* br2  = (const float*)d_in[11];
    const float* Wg1  = (const float*)d_in[12];
    const float* bg1  = (const float*)d_in[13];
    const float* Wrel = (const float*)d_in[14];
    const float* brel = (const float*)d_in[15];
    const float* Wroot= (const float*)d_in[16];
    const float* Wc0  = (const float*)d_in[17];
    const float* Wc1  = (const float*)d_in[18];
    const float* Wc2  = (const float*)d_in[19];
    const float* bc   = (const float*)d_in[20];

    size_t smem = sizeof(SM) > sizeof(HSM) ? sizeof(SM) : sizeof(HSM);
    cudaFuncSetAttribute(brain_kernel, cudaFuncAttributeMaxDynamicSharedMemorySize, (int)smem);
    brain_kernel<<<1 + MMB, NT, smem>>>(x, Wl1, Wr1, ei, ea, bl1, br1, Wl2, bl2,
                                        Wr2, br2, Wg1, bg1, Wrel, brel, Wroot,
                                        Wc0, Wc1, Wc2, bc, (float*)d_out);
}